// round 1
// baseline (speedup 1.0000x reference)
#include <cuda_runtime.h>
#include <math.h>

#define BZ 2
#define CC 128
#define NN 2304
#define WIMG 48

// ---------------- scratch (no allocations allowed) ----------------
__device__ float g_D[BZ * CC * NN];               // grid-sampled db, layout [b][c][n]
__device__ float g_hist[(size_t)BZ * 18 * 52 * NN]; // partial hists [b][mt][slot][n]
__device__ float g_part[18];                      // per-block loss partials

// ---------------- kernel 1: grid_sample (bilinear, zeros pad, align_corners=False) ----
__global__ void k_gridsample(const float* __restrict__ img2,
                             const float* __restrict__ grid) {
    int n = blockIdx.x;          // 0..2303
    int b = blockIdx.y;          // 0..1
    int c = threadIdx.x;         // 0..127

    float gx = grid[((size_t)b * NN + n) * 2 + 0];
    float gy = grid[((size_t)b * NN + n) * 2 + 1];
    float ix = fmaf(gx, 24.0f, 23.5f);   // ((gx+1)*48-1)*0.5
    float iy = fmaf(gy, 24.0f, 23.5f);
    float x0f = floorf(ix), y0f = floorf(iy);
    float wx = ix - x0f, wy = iy - y0f;
    int x0 = (int)x0f, y0 = (int)y0f;
    int x1 = x0 + 1,  y1 = y0 + 1;

    bool vx0 = (x0 >= 0) & (x0 < WIMG);
    bool vx1 = (x1 >= 0) & (x1 < WIMG);
    bool vy0 = (y0 >= 0) & (y0 < WIMG);
    bool vy1 = (y1 >= 0) & (y1 < WIMG);

    float w00 = (vx0 & vy0) ? (1.f - wx) * (1.f - wy) : 0.f;
    float w10 = (vx1 & vy0) ? wx * (1.f - wy)         : 0.f;
    float w01 = (vx0 & vy1) ? (1.f - wx) * wy         : 0.f;
    float w11 = (vx1 & vy1) ? wx * wy                 : 0.f;

    int cx0 = min(max(x0, 0), WIMG - 1), cx1 = min(max(x1, 0), WIMG - 1);
    int cy0 = min(max(y0, 0), WIMG - 1), cy1 = min(max(y1, 0), WIMG - 1);

    const float* im = img2 + ((size_t)b * CC + c) * NN;
    float v = w00 * im[cy0 * WIMG + cx0] + w10 * im[cy0 * WIMG + cx1]
            + w01 * im[cy1 * WIMG + cx0] + w11 * im[cy1 * WIMG + cx1];
    g_D[((size_t)b * CC + c) * NN + n] = v;
}

// ---------------- kernel 2: fused GEMM + quantized binning ----------------
// block = (mt 0..17, nt 0..35, b 0..1). Tile: 64 n-rows x 128 m-cols, K=128.
// 256 threads; micro-tile 4x8.
// smem layout (floats):
//   Qs[16*64]  Ds[16*128]  Ss[64*129]  hN[26*256]  hR[26*256]  rc[128] (int)
#define SM_QS   0
#define SM_DS   (SM_QS + 16 * 64)
#define SM_SS   (SM_DS + 16 * 128)
#define SM_HN   (SM_SS + 64 * 129)
#define SM_HR   (SM_HN + 26 * 256)
#define SM_RC   (SM_HR + 26 * 256)
#define SM_TOT  (SM_RC + 128)

__global__ void __launch_bounds__(256, 2) k_main(const float* __restrict__ img1) {
    extern __shared__ float sm[];
    float* Qs = sm + SM_QS;
    float* Ds = sm + SM_DS;
    float* Ss = sm + SM_SS;
    float* hN = sm + SM_HN;
    float* hR = sm + SM_HR;
    int*   rc = (int*)(sm + SM_RC);

    const int t  = threadIdx.x;
    const int mt = blockIdx.x;
    const int nt = blockIdx.y;
    const int b  = blockIdx.z;
    const int m0 = mt * 128;
    const int n0 = nt * 64;

    // zero this thread's private hist columns (exclusive: no sync needed yet)
#pragma unroll
    for (int c = 0; c < 26; c++) { hN[c * 256 + t] = 0.f; hR[c * 256 + t] = 0.f; }

    // row/col of the m-tile (for label computation)
    if (t < 128) {
        int mg = m0 + t;
        int rm = mg / WIMG;
        rc[t] = (rm << 8) | (mg - rm * WIMG);
    }

    const float* Qg = img1 + (size_t)b * CC * NN;   // [c][n]
    const float* Dg = g_D  + (size_t)b * CC * NN;   // [c][n]

    const int ty = t >> 4;   // 0..15 -> rows ty*4..+4
    const int tx = t & 15;   // 0..15 -> cols tx*8..+8

    float acc[4][8];
#pragma unroll
    for (int i = 0; i < 4; i++)
#pragma unroll
        for (int j = 0; j < 8; j++) acc[i][j] = 0.f;

    for (int k0 = 0; k0 < CC; k0 += 16) {
        // stage Qs[16][64]
        {
            int kq = t >> 4, nq = t & 15;
            *(float4*)&Qs[kq * 64 + nq * 4] =
                *(const float4*)&Qg[(size_t)(k0 + kq) * NN + n0 + nq * 4];
        }
        // stage Ds[16][128]
#pragma unroll
        for (int it = 0; it < 2; it++) {
            int s = t + it * 256;
            int kd = s >> 5, md = s & 31;
            *(float4*)&Ds[kd * 128 + md * 4] =
                *(const float4*)&Dg[(size_t)(k0 + kd) * NN + m0 + md * 4];
        }
        __syncthreads();

#pragma unroll
        for (int kk = 0; kk < 16; kk++) {
            float4 a4 = *(float4*)&Qs[kk * 64 + ty * 4];
            float4 b0 = *(float4*)&Ds[kk * 128 + tx * 8];
            float4 b1 = *(float4*)&Ds[kk * 128 + tx * 8 + 4];
            float av[4] = {a4.x, a4.y, a4.z, a4.w};
            float bv[8] = {b0.x, b0.y, b0.z, b0.w, b1.x, b1.y, b1.z, b1.w};
#pragma unroll
            for (int i = 0; i < 4; i++)
#pragma unroll
                for (int j = 0; j < 8; j++)
                    acc[i][j] = fmaf(av[i], bv[j], acc[i][j]);
        }
        __syncthreads();
    }

    // write S tile to shared (pad 129 -> conflict-free column reads)
#pragma unroll
    for (int i = 0; i < 4; i++)
#pragma unroll
        for (int j = 0; j < 8; j++)
            Ss[(ty * 4 + i) * 129 + tx * 8 + j] = acc[i][j];
    __syncthreads();

    // ---- phase B: binning. warp w: row-half = w&1, m-quarter = w>>1 ----
    {
        int w  = t >> 5;
        int ln = t & 31;
        int r  = ((w & 1) << 5) | ln;    // 0..63 (lane = row -> conflict-free)
        int mq = w >> 1;                  // 0..3
        int ng = n0 + r;
        int rn = ng / WIMG;
        int cn = ng - rn * WIMG;
        float* hNc = hN + t;
        float* hRc = hR + t;
#pragma unroll 4
        for (int m = 0; m < 32; m++) {
            int ml = mq * 32 + m;
            float s = Ss[r * 129 + ml];
            int rcm = rc[ml];
            int dr = (rcm >> 8) - rn;
            int dc = (rcm & 255) - cn;
            bool lab = (abs(dr) <= 4) && (abs(dc) <= 4);
            float tq = fmaf(s, -12.f, 12.f);        // t = 12(1-s)
            tq = fminf(fmaxf(tq, 0.f), 24.f);
            float cf = floorf(tq);
            int c0 = (int)cf;
            float whi = tq - cf;
            float wlo = 1.f - whi;
            hNc[c0 * 256]       += wlo;
            hNc[c0 * 256 + 256] += whi;
            if (lab) {
                hRc[c0 * 256]       += wlo;
                hRc[c0 * 256 + 256] += whi;
            }
        }
    }
    __syncthreads();

    // ---- reduce 4 m-quarter partials per row, store partial hist to global ----
    // slot 0..25 = nbs bins (25 used + spill), 26..51 = rec bins
    float* outp = g_hist + ((size_t)(b * 18 + mt) * 52) * NN;
#pragma unroll
    for (int kk = 0; kk < 13; kk++) {
        int idx  = t + kk * 256;      // 0..3327 = 52*64
        int slot = idx >> 6;          // 0..51
        int rr   = idx & 63;          // row in tile
        float* hh = (slot < 26) ? (hN + slot * 256) : (hR + (slot - 26) * 256);
        float v = 0.f;
#pragma unroll
        for (int q = 0; q < 4; q++) {
            int tq_ = ((((q << 1) | (rr >> 5)) << 5) | (rr & 31));
            v += hh[tq_];
        }
        outp[(size_t)slot * NN + n0 + rr] = v;
    }
}

// ---------------- kernel 3: per-row AP + loss, block-reduce ----------------
__global__ void k_final1(const float* __restrict__ rel) {
    int id = blockIdx.x * 256 + threadIdx.x;   // 0..4607
    int b = id / NN;
    int n = id - b * NN;
    const float* hb = g_hist + (size_t)b * 18 * 52 * NN;

    float cumn = 0.f, cumr = 0.f, sap = 0.f, sr = 0.f;
#pragma unroll 1
    for (int c = 0; c < 25; c++) {
        float nb = 0.f, rcv = 0.f;
#pragma unroll
        for (int mtv = 0; mtv < 18; mtv++) {
            nb  += hb[((size_t)(mtv * 52) + c) * NN + n];
            rcv += hb[((size_t)(mtv * 52) + 26 + c) * NN + n];
        }
        cumn += nb;
        cumr += rcv;
        float prec = cumr / (1e-16f + cumn);
        sap = fmaf(prec, rcv, sap);
        sr += rcv;
    }
    float ap = sap / sr;
    float rl = rel[(size_t)b * NN + n];
    float loss = 1.f - (ap * rl + 0.5f * (1.f - rl));

    __shared__ float red[256];
    red[threadIdx.x] = loss;
    __syncthreads();
#pragma unroll
    for (int s = 128; s > 0; s >>= 1) {
        if (threadIdx.x < s) red[threadIdx.x] += red[threadIdx.x + s];
        __syncthreads();
    }
    if (threadIdx.x == 0) g_part[blockIdx.x] = red[0];
}

// ---------------- kernel 4: deterministic final reduction ----------------
__global__ void k_final2(float* __restrict__ out) {
    float v = (threadIdx.x < 18) ? g_part[threadIdx.x] : 0.f;
#pragma unroll
    for (int o = 16; o > 0; o >>= 1) v += __shfl_down_sync(0xffffffffu, v, o);
    if (threadIdx.x == 0) out[0] = v * (1.0f / 4608.0f);
}

// ---------------- launch ----------------
extern "C" void kernel_launch(void* const* d_in, const int* in_sizes, int n_in,
                              void* d_out, int out_size) {
    const float* img1 = (const float*)d_in[0];  // image1_descriptor (B,C,H,W)
    const float* img2 = (const float*)d_in[1];  // image2_descriptor (B,C,H,W)
    const float* rel  = (const float*)d_in[2];  // reliability (B,1,H,W)
    const float* grid = (const float*)d_in[3];  // grid (B,H,W,2)

    cudaFuncSetAttribute(k_main, cudaFuncAttributeMaxDynamicSharedMemorySize,
                         SM_TOT * (int)sizeof(float));

    k_gridsample<<<dim3(NN, BZ), 128>>>(img2, grid);
    k_main<<<dim3(18, 36, 2), 256, SM_TOT * (int)sizeof(float)>>>(img1);
    k_final1<<<18, 256>>>(rel);
    k_final2<<<1, 32>>>((float*)d_out);
}

// round 3
// speedup vs baseline: 1.6687x; 1.6687x over previous
#include <cuda_runtime.h>
#include <math.h>
#include <stdint.h>

#define BZ 2
#define CC 128
#define NN 2304
#define WIMG 48

// ---------------- scratch (no allocations allowed) ----------------
__device__ float g_D[BZ * CC * NN];                  // grid-sampled db, [b][c][n]
__device__ float g_hist[(size_t)BZ * 18 * 52 * NN];  // partial hists [b][mt][slot][n]
__device__ float g_part[36];                         // per-block loss partials
__device__ unsigned g_ctr = 0;

// ---------------- kernel 1: grid_sample (bilinear, zero pad, align_corners=False) ----
__global__ void k_gridsample(const float* __restrict__ img2,
                             const float* __restrict__ grid) {
    int n = blockIdx.x;          // 0..2303
    int b = blockIdx.y;          // 0..1
    int c = threadIdx.x;         // 0..127

    float gx = grid[((size_t)b * NN + n) * 2 + 0];
    float gy = grid[((size_t)b * NN + n) * 2 + 1];
    float ix = fmaf(gx, 24.0f, 23.5f);
    float iy = fmaf(gy, 24.0f, 23.5f);
    float x0f = floorf(ix), y0f = floorf(iy);
    float wx = ix - x0f, wy = iy - y0f;
    int x0 = (int)x0f, y0 = (int)y0f;
    int x1 = x0 + 1,  y1 = y0 + 1;

    bool vx0 = (x0 >= 0) & (x0 < WIMG);
    bool vx1 = (x1 >= 0) & (x1 < WIMG);
    bool vy0 = (y0 >= 0) & (y0 < WIMG);
    bool vy1 = (y1 >= 0) & (y1 < WIMG);

    float w00 = (vx0 & vy0) ? (1.f - wx) * (1.f - wy) : 0.f;
    float w10 = (vx1 & vy0) ? wx * (1.f - wy)         : 0.f;
    float w01 = (vx0 & vy1) ? (1.f - wx) * wy         : 0.f;
    float w11 = (vx1 & vy1) ? wx * wy                 : 0.f;

    int cx0 = min(max(x0, 0), WIMG - 1), cx1 = min(max(x1, 0), WIMG - 1);
    int cy0 = min(max(y0, 0), WIMG - 1), cy1 = min(max(y1, 0), WIMG - 1);

    const float* im = img2 + ((size_t)b * CC + c) * NN;
    float v = w00 * im[cy0 * WIMG + cx0] + w10 * im[cy0 * WIMG + cx1]
            + w01 * im[cy1 * WIMG + cx0] + w11 * im[cy1 * WIMG + cx1];
    g_D[((size_t)b * CC + c) * NN + n] = v;
}

// ---------------- tf32 helpers ----------------
__device__ __forceinline__ uint32_t f2tf32(float x) {
    uint32_t r;
    asm("cvt.rna.tf32.f32 %0, %1;" : "=r"(r) : "f"(x));
    return r;
}

__device__ __forceinline__ void mma_tf32(float* d,
                                         uint32_t a0, uint32_t a1, uint32_t a2, uint32_t a3,
                                         uint32_t b0, uint32_t b1) {
    asm volatile(
        "mma.sync.aligned.m16n8k8.row.col.f32.tf32.tf32.f32 "
        "{%0,%1,%2,%3}, {%4,%5,%6,%7}, {%8,%9}, {%0,%1,%2,%3};"
        : "+f"(d[0]), "+f"(d[1]), "+f"(d[2]), "+f"(d[3])
        : "r"(a0), "r"(a1), "r"(a2), "r"(a3), "r"(b0), "r"(b1));
}

// ---------------- kernel 2: fused HMMA-tf32 GEMM + quantized binning ----------------
// block = (mt 0..17, nt 0..35, b 0..1). Tile: 64 n-rows x 128 m-cols, K=128 in 32-chunks.
// smem (floats): Ss[64*129] | hN[26*256] | hR[26*256] | rc[128]
// GEMM staging (As[32*72], Bs[32*136]) aliases the hN/hR region (zeroed after GEMM).
#define SM_SS   0
#define SM_HN   (SM_SS + 64 * 129)
#define SM_HR   (SM_HN + 26 * 256)
#define SM_RC   (SM_HR + 26 * 256)
#define SM_TOT  (SM_RC + 128)
#define APAD 72
#define BPAD 136

__global__ void __launch_bounds__(256, 2) k_main(const float* __restrict__ img1) {
    extern __shared__ float smf[];
    float*    Ss = smf + SM_SS;
    float*    hN = smf + SM_HN;
    float*    hR = smf + SM_HR;
    int*      rc = (int*)(smf + SM_RC);
    uint32_t* As = (uint32_t*)(smf + SM_HN);            // 32*72  = 2304
    uint32_t* Bs = (uint32_t*)(smf + SM_HN + 32 * APAD); // 32*136 = 4352

    const int t  = threadIdx.x;
    const int w  = t >> 5;
    const int ln = t & 31;
    const int mt = blockIdx.x;
    const int nt = blockIdx.y;
    const int b  = blockIdx.z;
    const int m0 = mt * 128;
    const int n0 = nt * 64;

    if (t < 128) {
        int mg = m0 + t;
        int rm = mg / WIMG;
        rc[t] = (rm << 8) | (mg - rm * WIMG);
    }

    const float* Qg = img1 + (size_t)b * CC * NN + n0;   // [c][n] slice
    const float* Dg = g_D  + (size_t)b * CC * NN + m0;   // [c][n] slice

    const int g  = ln >> 2;       // groupID 0..7
    const int tg = ln & 3;        // thread-in-group 0..3
    const int nbw = (w & 1) * 32; // warp row base (n)
    const int mbw = (w >> 1) * 32;// warp col base (m)

    float acc[2][4][4];
#pragma unroll
    for (int i = 0; i < 2; i++)
#pragma unroll
        for (int j = 0; j < 4; j++)
#pragma unroll
            for (int k = 0; k < 4; k++) acc[i][j][k] = 0.f;

    for (int k0 = 0; k0 < CC; k0 += 32) {
        // stage As[32][64] (k-major, pad 72): 512 float4
#pragma unroll
        for (int i = 0; i < 2; i++) {
            int idx = t + i * 256;           // float4 index
            int k  = idx >> 4;
            int n4 = (idx & 15) << 2;
            float4 v = *(const float4*)&Qg[(size_t)(k0 + k) * NN + n4];
            uint32_t* p = As + k * APAD + n4;
            p[0] = f2tf32(v.x); p[1] = f2tf32(v.y);
            p[2] = f2tf32(v.z); p[3] = f2tf32(v.w);
        }
        // stage Bs[32][128] (k-major, pad 136): 1024 float4
#pragma unroll
        for (int i = 0; i < 4; i++) {
            int idx = t + i * 256;
            int k  = idx >> 5;
            int m4 = (idx & 31) << 2;
            float4 v = *(const float4*)&Dg[(size_t)(k0 + k) * NN + m4];
            uint32_t* p = Bs + k * BPAD + m4;
            p[0] = f2tf32(v.x); p[1] = f2tf32(v.y);
            p[2] = f2tf32(v.z); p[3] = f2tf32(v.w);
        }
        __syncthreads();

#pragma unroll
        for (int kk = 0; kk < 4; kk++) {
            int ka = kk * 8 + tg;
            // A fragments: 2 row-tiles
            uint32_t af[2][4];
#pragma unroll
            for (int rt = 0; rt < 2; rt++) {
                int nb = nbw + rt * 16 + g;
                af[rt][0] = As[ka * APAD + nb];
                af[rt][1] = As[ka * APAD + nb + 8];
                af[rt][2] = As[(ka + 4) * APAD + nb];
                af[rt][3] = As[(ka + 4) * APAD + nb + 8];
            }
            // B fragments: 4 col-tiles
            uint32_t bf[4][2];
#pragma unroll
            for (int ct = 0; ct < 4; ct++) {
                int mb = mbw + ct * 8 + g;
                bf[ct][0] = Bs[ka * BPAD + mb];
                bf[ct][1] = Bs[(ka + 4) * BPAD + mb];
            }
#pragma unroll
            for (int rt = 0; rt < 2; rt++)
#pragma unroll
                for (int ct = 0; ct < 4; ct++)
                    mma_tf32(acc[rt][ct], af[rt][0], af[rt][1], af[rt][2], af[rt][3],
                             bf[ct][0], bf[ct][1]);
        }
        __syncthreads();
    }

    // ---- write S tile to shared from HMMA fragments ----
#pragma unroll
    for (int rt = 0; rt < 2; rt++) {
        int row = nbw + rt * 16 + g;
#pragma unroll
        for (int ct = 0; ct < 4; ct++) {
            int col = mbw + ct * 8 + tg * 2;
            Ss[row * 129 + col]           = acc[rt][ct][0];
            Ss[row * 129 + col + 1]       = acc[rt][ct][1];
            Ss[(row + 8) * 129 + col]     = acc[rt][ct][2];
            Ss[(row + 8) * 129 + col + 1] = acc[rt][ct][3];
        }
    }
    __syncthreads();

    // ---- zero private hist columns (aliased w/ staging, so zero here) ----
#pragma unroll
    for (int c = 0; c < 26; c++) { hN[c * 256 + t] = 0.f; hR[c * 256 + t] = 0.f; }
    // no sync needed: each thread uses only its own column

    // ---- binning: warp w -> row-half = w&1, m-quarter = w>>1 ----
    {
        int r  = ((w & 1) << 5) | ln;
        int mq = w >> 1;
        int ng = n0 + r;
        int rn = ng / WIMG;
        int cn = ng - rn * WIMG;
        float* hNc = hN + t;
        float* hRc = hR + t;
#pragma unroll 4
        for (int m = 0; m < 32; m++) {
            int ml = mq * 32 + m;
            float s = Ss[r * 129 + ml];
            int rcm = rc[ml];
            int dr = (rcm >> 8) - rn;
            int dc = (rcm & 255) - cn;
            bool lab = (abs(dr) <= 4) && (abs(dc) <= 4);
            float tq = fmaf(s, -12.f, 12.f);
            tq = fminf(fmaxf(tq, 0.f), 24.f);
            float cf = floorf(tq);
            int c0 = (int)cf;
            float whi = tq - cf;
            float wlo = 1.f - whi;
            hNc[c0 * 256]       += wlo;
            hNc[c0 * 256 + 256] += whi;
            if (lab) {
                hRc[c0 * 256]       += wlo;
                hRc[c0 * 256 + 256] += whi;
            }
        }
    }
    __syncthreads();

    // ---- reduce 4 m-quarter partials per row, store partial hist to global ----
    float* outp = g_hist + ((size_t)(b * 18 + mt) * 52) * NN;
#pragma unroll
    for (int kk = 0; kk < 13; kk++) {
        int idx  = t + kk * 256;
        int slot = idx >> 6;
        int rr   = idx & 63;
        float* hh = (slot < 26) ? (hN + slot * 256) : (hR + (slot - 26) * 256);
        float v = 0.f;
#pragma unroll
        for (int q = 0; q < 4; q++) {
            int tq_ = ((((q << 1) | (rr >> 5)) << 5) | (rr & 31));
            v += hh[tq_];
        }
        outp[(size_t)slot * NN + n0 + rr] = v;
    }
}

// ---------------- kernel 3: per-row AP + loss + last-block final reduce ----------------
__global__ void k_final1(const float* __restrict__ rel, float* __restrict__ out) {
    int id = blockIdx.x * 128 + threadIdx.x;   // 0..4607
    int b = id / NN;
    int n = id - b * NN;
    const float* hb = g_hist + (size_t)b * 18 * 52 * NN;

    float cumn = 0.f, cumr = 0.f, sap = 0.f, sr = 0.f;
#pragma unroll 1
    for (int c = 0; c < 25; c++) {
        float nb = 0.f, rcv = 0.f;
#pragma unroll
        for (int mtv = 0; mtv < 18; mtv++) {
            nb  += hb[((size_t)(mtv * 52) + c) * NN + n];
            rcv += hb[((size_t)(mtv * 52) + 26 + c) * NN + n];
        }
        cumn += nb;
        cumr += rcv;
        float prec = cumr / (1e-16f + cumn);
        sap = fmaf(prec, rcv, sap);
        sr += rcv;
    }
    float ap = sap / sr;
    float rl = rel[(size_t)b * NN + n];
    float loss = 1.f - (ap * rl + 0.5f * (1.f - rl));

    __shared__ float red[128];
    red[threadIdx.x] = loss;
    __syncthreads();
#pragma unroll
    for (int s = 64; s > 0; s >>= 1) {
        if (threadIdx.x < s) red[threadIdx.x] += red[threadIdx.x + s];
        __syncthreads();
    }
    if (threadIdx.x == 0) {
        g_part[blockIdx.x] = red[0];
        __threadfence();
        unsigned old = atomicAdd(&g_ctr, 1u);
        if (old == 35u) {
            __threadfence();
            float ssum = 0.f;
#pragma unroll
            for (int i = 0; i < 36; i++) ssum += g_part[i];
            out[0] = ssum * (1.0f / 4608.0f);
            g_ctr = 0u;
        }
    }
}

// ---------------- launch ----------------
extern "C" void kernel_launch(void* const* d_in, const int* in_sizes, int n_in,
                              void* d_out, int out_size) {
    const float* img1 = (const float*)d_in[0];  // image1_descriptor (B,C,H,W)
    const float* img2 = (const float*)d_in[1];  // image2_descriptor (B,C,H,W)
    const float* rel  = (const float*)d_in[2];  // reliability (B,1,H,W)
    const float* grid = (const float*)d_in[3];  // grid (B,H,W,2)

    cudaFuncSetAttribute(k_main, cudaFuncAttributeMaxDynamicSharedMemorySize,
                         SM_TOT * (int)sizeof(float));

    k_gridsample<<<dim3(NN, BZ), 128>>>(img2, grid);
    k_main<<<dim3(18, 36, BZ), 256, SM_TOT * (int)sizeof(float)>>>(img1);
    k_final1<<<36, 128>>>(rel, (float*)d_out);
}

// round 4
// speedup vs baseline: 1.9488x; 1.1679x over previous
#include <cuda_runtime.h>
#include <cuda_fp16.h>
#include <math.h>
#include <stdint.h>

#define BZ 2
#define CC 128
#define NN 2304
#define WIMG 48

// ---------------- scratch (no allocations allowed) ----------------
__device__ __half g_Qh[BZ * NN * CC];                // img1 transposed -> [b][n][c] half
__device__ __half g_Th[BZ * NN * CC];                // img2 transposed -> [b][p][c] half
__device__ __half g_Dh[BZ * NN * CC];                // grid-sampled db  [b][n][c] half
__device__ float g_hist[(size_t)BZ * 18 * 52 * NN];  // partial hists [b][mt][slot][n]
__device__ float g_part[36];
__device__ unsigned g_ctr = 0;

// ---------------- kernel 1: transpose [b][c][p] -> [b][p][c] + cvt to half ----------
__global__ void k_prep(const float* __restrict__ img1, const float* __restrict__ img2) {
    __shared__ float tile[32][33];
    int img = blockIdx.z & 1;
    int b   = blockIdx.z >> 1;
    const float* in = (img == 0 ? img1 : img2) + (size_t)b * CC * NN;
    __half* out     = (img == 0 ? g_Qh : g_Th) + (size_t)b * NN * CC;

    int p0 = blockIdx.x * 32;
    int c0 = blockIdx.y * 32;
    int tx = threadIdx.x, ty = threadIdx.y;

#pragma unroll
    for (int j = 0; j < 4; j++)
        tile[ty + j * 8][tx] = in[(size_t)(c0 + ty + j * 8) * NN + p0 + tx];
    __syncthreads();
#pragma unroll
    for (int j = 0; j < 4; j++)
        out[(size_t)(p0 + ty + j * 8) * CC + c0 + tx] =
            __float2half(tile[tx][ty + j * 8]);
}

// ---------------- kernel 2: grid_sample, warp-per-point, coalesced ----------------
__global__ void k_gridsample(const float* __restrict__ grid) {
    int w    = threadIdx.x >> 5;
    int lane = threadIdx.x & 31;
    int n = blockIdx.x * 8 + w;           // 0..2303
    int b = blockIdx.y;

    float gx = grid[((size_t)b * NN + n) * 2 + 0];
    float gy = grid[((size_t)b * NN + n) * 2 + 1];
    float ix = fmaf(gx, 24.0f, 23.5f);
    float iy = fmaf(gy, 24.0f, 23.5f);
    float x0f = floorf(ix), y0f = floorf(iy);
    float wx = ix - x0f, wy = iy - y0f;
    int x0 = (int)x0f, y0 = (int)y0f;
    int x1 = x0 + 1,  y1 = y0 + 1;

    bool vx0 = (x0 >= 0) & (x0 < WIMG);
    bool vx1 = (x1 >= 0) & (x1 < WIMG);
    bool vy0 = (y0 >= 0) & (y0 < WIMG);
    bool vy1 = (y1 >= 0) & (y1 < WIMG);

    float w00 = (vx0 & vy0) ? (1.f - wx) * (1.f - wy) : 0.f;
    float w10 = (vx1 & vy0) ? wx * (1.f - wy)         : 0.f;
    float w01 = (vx0 & vy1) ? (1.f - wx) * wy         : 0.f;
    float w11 = (vx1 & vy1) ? wx * wy                 : 0.f;

    int cx0 = min(max(x0, 0), WIMG - 1), cx1 = min(max(x1, 0), WIMG - 1);
    int cy0 = min(max(y0, 0), WIMG - 1), cy1 = min(max(y1, 0), WIMG - 1);

    const __half* T = g_Th + (size_t)b * NN * CC;
    int p00 = cy0 * WIMG + cx0, p10 = cy0 * WIMG + cx1;
    int p01 = cy1 * WIMG + cx0, p11 = cy1 * WIMG + cx1;

    uint2 v00 = ((const uint2*)(T + (size_t)p00 * CC))[lane];
    uint2 v10 = ((const uint2*)(T + (size_t)p10 * CC))[lane];
    uint2 v01 = ((const uint2*)(T + (size_t)p01 * CC))[lane];
    uint2 v11 = ((const uint2*)(T + (size_t)p11 * CC))[lane];

    float r[4];
#pragma unroll
    for (int h = 0; h < 2; h++) {
        float2 f00 = __half22float2(((__half2*)&v00)[h]);
        float2 f10 = __half22float2(((__half2*)&v10)[h]);
        float2 f01 = __half22float2(((__half2*)&v01)[h]);
        float2 f11 = __half22float2(((__half2*)&v11)[h]);
        r[2 * h + 0] = w00 * f00.x + w10 * f10.x + w01 * f01.x + w11 * f11.x;
        r[2 * h + 1] = w00 * f00.y + w10 * f10.y + w01 * f01.y + w11 * f11.y;
    }
    uint2 o;
    ((__half2*)&o)[0] = __floats2half2_rn(r[0], r[1]);
    ((__half2*)&o)[1] = __floats2half2_rn(r[2], r[3]);
    ((uint2*)(g_Dh + ((size_t)b * NN + n) * CC))[lane] = o;
}

// ---------------- fp16 MMA helper ----------------
__device__ __forceinline__ void mma_f16(float* d, const uint32_t* a, const uint32_t* bb) {
    asm volatile(
        "mma.sync.aligned.m16n8k16.row.col.f32.f16.f16.f32 "
        "{%0,%1,%2,%3}, {%4,%5,%6,%7}, {%8,%9}, {%0,%1,%2,%3};"
        : "+f"(d[0]), "+f"(d[1]), "+f"(d[2]), "+f"(d[3])
        : "r"(a[0]), "r"(a[1]), "r"(a[2]), "r"(a[3]), "r"(bb[0]), "r"(bb[1]));
}

// ---------------- kernel 3: fused fp16-HMMA GEMM + quantized binning ----------------
// block = (mt 0..17, nt 0..35, b). Tile: 64 n-rows x 128 m-cols, K=128 in 32-chunks.
// smem (floats): Ss[64*129] | hN[26*256] | hR[26*256] | rc[128]
// staging As2[64*20] u32 aliases hN, Bs2[128*20] u32 aliases hR.
#define SM_SS   0
#define SM_HN   (SM_SS + 64 * 129)
#define SM_HR   (SM_HN + 26 * 256)
#define SM_RC   (SM_HR + 26 * 256)
#define SM_TOT  (SM_RC + 128)
#define KPAD 20

__global__ void __launch_bounds__(256, 2) k_main() {
    extern __shared__ float smf[];
    float*    Ss  = smf + SM_SS;
    float*    hN  = smf + SM_HN;
    float*    hR  = smf + SM_HR;
    int*      rc  = (int*)(smf + SM_RC);
    uint32_t* As2 = (uint32_t*)(smf + SM_HN);   // 64*20  = 1280 words
    uint32_t* Bs2 = (uint32_t*)(smf + SM_HR);   // 128*20 = 2560 words

    const int t  = threadIdx.x;
    const int w  = t >> 5;
    const int ln = t & 31;
    const int mt = blockIdx.x;
    const int nt = blockIdx.y;
    const int b  = blockIdx.z;
    const int m0 = mt * 128;
    const int n0 = nt * 64;

    if (t < 128) {
        int mg = m0 + t;
        int rm = mg / WIMG;
        rc[t] = (rm << 8) | (mg - rm * WIMG);
    }

    const int g   = ln >> 2;        // 0..7
    const int tg  = ln & 3;         // 0..3
    const int nbw = (w & 1) * 32;
    const int mbw = (w >> 1) * 32;

    float acc[2][4][4];
#pragma unroll
    for (int i = 0; i < 2; i++)
#pragma unroll
        for (int j = 0; j < 4; j++)
#pragma unroll
            for (int k = 0; k < 4; k++) acc[i][j][k] = 0.f;

    const __half* Qh = g_Qh + ((size_t)b * NN + n0) * CC;
    const __half* Dh = g_Dh + ((size_t)b * NN + m0) * CC;

    for (int k0 = 0; k0 < CC; k0 += 32) {
        // stage A: 64 rows x 16 k2-words = 256 uint4 (1/thread)
        {
            int nrow = t >> 2, c4 = t & 3;
            uint4 v = ((const uint4*)(Qh + (size_t)nrow * CC + k0))[c4];
            *(uint4*)&As2[nrow * KPAD + c4 * 4] = v;
        }
        // stage B: 128 rows x 16 k2-words = 512 uint4 (2/thread)
#pragma unroll
        for (int i = 0; i < 2; i++) {
            int idx = t + i * 256;
            int m = idx >> 2, c4 = idx & 3;
            uint4 v = ((const uint4*)(Dh + (size_t)m * CC + k0))[c4];
            *(uint4*)&Bs2[m * KPAD + c4 * 4] = v;
        }
        __syncthreads();

#pragma unroll
        for (int kk = 0; kk < 2; kk++) {
            int kb = kk * 8 + tg;
            uint32_t af[2][4];
#pragma unroll
            for (int rt = 0; rt < 2; rt++) {
                int nb = nbw + rt * 16 + g;
                af[rt][0] = As2[nb * KPAD + kb];
                af[rt][1] = As2[(nb + 8) * KPAD + kb];
                af[rt][2] = As2[nb * KPAD + kb + 4];
                af[rt][3] = As2[(nb + 8) * KPAD + kb + 4];
            }
            uint32_t bf[4][2];
#pragma unroll
            for (int ct = 0; ct < 4; ct++) {
                int mb = mbw + ct * 8 + g;
                bf[ct][0] = Bs2[mb * KPAD + kb];
                bf[ct][1] = Bs2[mb * KPAD + kb + 4];
            }
#pragma unroll
            for (int rt = 0; rt < 2; rt++)
#pragma unroll
                for (int ct = 0; ct < 4; ct++)
                    mma_f16(acc[rt][ct], af[rt], bf[ct]);
        }
        __syncthreads();
    }

    // ---- write S tile to shared from HMMA fragments ----
#pragma unroll
    for (int rt = 0; rt < 2; rt++) {
        int row = nbw + rt * 16 + g;
#pragma unroll
        for (int ct = 0; ct < 4; ct++) {
            int col = mbw + ct * 8 + tg * 2;
            Ss[row * 129 + col]           = acc[rt][ct][0];
            Ss[row * 129 + col + 1]       = acc[rt][ct][1];
            Ss[(row + 8) * 129 + col]     = acc[rt][ct][2];
            Ss[(row + 8) * 129 + col + 1] = acc[rt][ct][3];
        }
    }
    __syncthreads();

    // ---- zero private hist columns (aliased w/ staging) ----
#pragma unroll
    for (int c = 0; c < 26; c++) { hN[c * 256 + t] = 0.f; hR[c * 256 + t] = 0.f; }

    // ---- binning: warp w -> row-half = w&1, m-quarter = w>>1 ----
    {
        int r  = ((w & 1) << 5) | ln;
        int mq = w >> 1;
        int ng = n0 + r;
        int rn = ng / WIMG;
        int cn = ng - rn * WIMG;
        float* hNc = hN + t;
        float* hRc = hR + t;
#pragma unroll 4
        for (int m = 0; m < 32; m++) {
            int ml = mq * 32 + m;
            float s = Ss[r * 129 + ml];
            int rcm = rc[ml];
            int dr = (rcm >> 8) - rn;
            int dc = (rcm & 255) - cn;
            bool lab = (abs(dr) <= 4) && (abs(dc) <= 4);
            float tq = fmaf(s, -12.f, 12.f);
            tq = fminf(fmaxf(tq, 0.f), 24.f);
            float cf = floorf(tq);
            int c0 = (int)cf;
            float whi = tq - cf;
            float wlo = 1.f - whi;
            hNc[c0 * 256]       += wlo;
            hNc[c0 * 256 + 256] += whi;
            if (lab) {
                hRc[c0 * 256]       += wlo;
                hRc[c0 * 256 + 256] += whi;
            }
        }
    }
    __syncthreads();

    // ---- reduce 4 m-quarter partials per row, store partial hist to global ----
    float* outp = g_hist + ((size_t)(b * 18 + mt) * 52) * NN;
#pragma unroll
    for (int kk = 0; kk < 13; kk++) {
        int idx  = t + kk * 256;
        int slot = idx >> 6;
        int rr   = idx & 63;
        float* hh = (slot < 26) ? (hN + slot * 256) : (hR + (slot - 26) * 256);
        float v = 0.f;
#pragma unroll
        for (int q = 0; q < 4; q++) {
            int tq_ = ((((q << 1) | (rr >> 5)) << 5) | (rr & 31));
            v += hh[tq_];
        }
        outp[(size_t)slot * NN + n0 + rr] = v;
    }
}

// ---------------- kernel 4: per-row AP + loss + last-block final reduce ----------------
__global__ void k_final1(const float* __restrict__ rel, float* __restrict__ out) {
    int id = blockIdx.x * 128 + threadIdx.x;   // 0..4607
    int b = id / NN;
    int n = id - b * NN;
    const float* hb = g_hist + (size_t)b * 18 * 52 * NN;

    float cumn = 0.f, cumr = 0.f, sap = 0.f, sr = 0.f;
#pragma unroll 1
    for (int c = 0; c < 25; c++) {
        float nb = 0.f, rcv = 0.f;
#pragma unroll
        for (int mtv = 0; mtv < 18; mtv++) {
            nb  += hb[((size_t)(mtv * 52) + c) * NN + n];
            rcv += hb[((size_t)(mtv * 52) + 26 + c) * NN + n];
        }
        cumn += nb;
        cumr += rcv;
        float prec = cumr / (1e-16f + cumn);
        sap = fmaf(prec, rcv, sap);
        sr += rcv;
    }
    float ap = sap / sr;
    float rl = rel[(size_t)b * NN + n];
    float loss = 1.f - (ap * rl + 0.5f * (1.f - rl));

    __shared__ float red[128];
    red[threadIdx.x] = loss;
    __syncthreads();
#pragma unroll
    for (int s = 64; s > 0; s >>= 1) {
        if (threadIdx.x < s) red[threadIdx.x] += red[threadIdx.x + s];
        __syncthreads();
    }
    if (threadIdx.x == 0) {
        g_part[blockIdx.x] = red[0];
        __threadfence();
        unsigned old = atomicAdd(&g_ctr, 1u);
        if (old == 35u) {
            __threadfence();
            float ssum = 0.f;
#pragma unroll
            for (int i = 0; i < 36; i++) ssum += g_part[i];
            out[0] = ssum * (1.0f / 4608.0f);
            g_ctr = 0u;
        }
    }
}

// ---------------- launch ----------------
extern "C" void kernel_launch(void* const* d_in, const int* in_sizes, int n_in,
                              void* d_out, int out_size) {
    const float* img1 = (const float*)d_in[0];
    const float* img2 = (const float*)d_in[1];
    const float* rel  = (const float*)d_in[2];
    const float* grid = (const float*)d_in[3];

    cudaFuncSetAttribute(k_main, cudaFuncAttributeMaxDynamicSharedMemorySize,
                         SM_TOT * (int)sizeof(float));

    k_prep<<<dim3(72, 4, 4), dim3(32, 8)>>>(img1, img2);
    k_gridsample<<<dim3(288, 2), 256>>>(grid);
    k_main<<<dim3(18, 36, BZ), 256, SM_TOT * (int)sizeof(float)>>>();
    k_final1<<<36, 128>>>(rel, (float*)d_out);
}

// round 5
// speedup vs baseline: 2.7473x; 1.4097x over previous
#include <cuda_runtime.h>
#include <cuda_fp16.h>
#include <math.h>
#include <stdint.h>

#define BZ 2
#define CC 128
#define NN 2304
#define WIMG 48

// ---------------- scratch (no allocations allowed) ----------------
__device__ __half g_Qh[BZ * NN * CC];                // img1 transposed -> [b][n][c] half
__device__ __half g_Th[BZ * NN * CC];                // img2 transposed -> [b][p][c] half
__device__ __half g_Dh[BZ * NN * CC];                // grid-sampled db  [b][n][c] half
__device__ float g_hist[(size_t)BZ * 18 * 52 * NN];  // partial hists [b][mt][slot][n]
__device__ float g_hist2[(size_t)BZ * 50 * NN];      // reduced hists [b][slot50][n]
__device__ float g_part[36];
__device__ unsigned g_ctr = 0;

// ---------------- kernel 1: transpose [b][c][p] -> [b][p][c] + cvt to half ----------
__global__ void k_prep(const float* __restrict__ img1, const float* __restrict__ img2) {
    __shared__ float tile[32][33];
    int img = blockIdx.z & 1;
    int b   = blockIdx.z >> 1;
    const float* in = (img == 0 ? img1 : img2) + (size_t)b * CC * NN;
    __half* out     = (img == 0 ? g_Qh : g_Th) + (size_t)b * NN * CC;

    int p0 = blockIdx.x * 32;
    int c0 = blockIdx.y * 32;
    int tx = threadIdx.x, ty = threadIdx.y;

#pragma unroll
    for (int j = 0; j < 4; j++)
        tile[ty + j * 8][tx] = in[(size_t)(c0 + ty + j * 8) * NN + p0 + tx];
    __syncthreads();
#pragma unroll
    for (int j = 0; j < 4; j++)
        out[(size_t)(p0 + ty + j * 8) * CC + c0 + tx] =
            __float2half(tile[tx][ty + j * 8]);
}

// ---------------- kernel 2: grid_sample, warp-per-point, coalesced ----------------
__global__ void k_gridsample(const float* __restrict__ grid) {
    int w    = threadIdx.x >> 5;
    int lane = threadIdx.x & 31;
    int n = blockIdx.x * 8 + w;           // 0..2303
    int b = blockIdx.y;

    float gx = grid[((size_t)b * NN + n) * 2 + 0];
    float gy = grid[((size_t)b * NN + n) * 2 + 1];
    float ix = fmaf(gx, 24.0f, 23.5f);
    float iy = fmaf(gy, 24.0f, 23.5f);
    float x0f = floorf(ix), y0f = floorf(iy);
    float wx = ix - x0f, wy = iy - y0f;
    int x0 = (int)x0f, y0 = (int)y0f;
    int x1 = x0 + 1,  y1 = y0 + 1;

    bool vx0 = (x0 >= 0) & (x0 < WIMG);
    bool vx1 = (x1 >= 0) & (x1 < WIMG);
    bool vy0 = (y0 >= 0) & (y0 < WIMG);
    bool vy1 = (y1 >= 0) & (y1 < WIMG);

    float w00 = (vx0 & vy0) ? (1.f - wx) * (1.f - wy) : 0.f;
    float w10 = (vx1 & vy0) ? wx * (1.f - wy)         : 0.f;
    float w01 = (vx0 & vy1) ? (1.f - wx) * wy         : 0.f;
    float w11 = (vx1 & vy1) ? wx * wy                 : 0.f;

    int cx0 = min(max(x0, 0), WIMG - 1), cx1 = min(max(x1, 0), WIMG - 1);
    int cy0 = min(max(y0, 0), WIMG - 1), cy1 = min(max(y1, 0), WIMG - 1);

    const __half* T = g_Th + (size_t)b * NN * CC;
    int p00 = cy0 * WIMG + cx0, p10 = cy0 * WIMG + cx1;
    int p01 = cy1 * WIMG + cx0, p11 = cy1 * WIMG + cx1;

    uint2 v00 = ((const uint2*)(T + (size_t)p00 * CC))[lane];
    uint2 v10 = ((const uint2*)(T + (size_t)p10 * CC))[lane];
    uint2 v01 = ((const uint2*)(T + (size_t)p01 * CC))[lane];
    uint2 v11 = ((const uint2*)(T + (size_t)p11 * CC))[lane];

    float r[4];
#pragma unroll
    for (int h = 0; h < 2; h++) {
        float2 f00 = __half22float2(((__half2*)&v00)[h]);
        float2 f10 = __half22float2(((__half2*)&v10)[h]);
        float2 f01 = __half22float2(((__half2*)&v01)[h]);
        float2 f11 = __half22float2(((__half2*)&v11)[h]);
        r[2 * h + 0] = w00 * f00.x + w10 * f10.x + w01 * f01.x + w11 * f11.x;
        r[2 * h + 1] = w00 * f00.y + w10 * f10.y + w01 * f01.y + w11 * f11.y;
    }
    uint2 o;
    ((__half2*)&o)[0] = __floats2half2_rn(r[0], r[1]);
    ((__half2*)&o)[1] = __floats2half2_rn(r[2], r[3]);
    ((uint2*)(g_Dh + ((size_t)b * NN + n) * CC))[lane] = o;
}

// ---------------- fp16 MMA helper ----------------
__device__ __forceinline__ void mma_f16(float* d, const uint32_t* a, const uint32_t* bb) {
    asm volatile(
        "mma.sync.aligned.m16n8k16.row.col.f32.f16.f16.f32 "
        "{%0,%1,%2,%3}, {%4,%5,%6,%7}, {%8,%9}, {%0,%1,%2,%3};"
        : "+f"(d[0]), "+f"(d[1]), "+f"(d[2]), "+f"(d[3])
        : "r"(a[0]), "r"(a[1]), "r"(a[2]), "r"(a[3]), "r"(bb[0]), "r"(bb[1]));
}

// ---------------- kernel 3: fused fp16-HMMA GEMM + quantized binning ----------------
#define SM_SS   0
#define SM_HN   (SM_SS + 64 * 129)
#define SM_HR   (SM_HN + 26 * 256)
#define SM_RC   (SM_HR + 26 * 256)
#define SM_TOT  (SM_RC + 128)
#define KPAD 20

__global__ void __launch_bounds__(256, 2) k_main() {
    extern __shared__ float smf[];
    float*    Ss  = smf + SM_SS;
    float*    hN  = smf + SM_HN;
    float*    hR  = smf + SM_HR;
    int*      rc  = (int*)(smf + SM_RC);
    uint32_t* As2 = (uint32_t*)(smf + SM_HN);   // 64*20  = 1280 words
    uint32_t* Bs2 = (uint32_t*)(smf + SM_HR);   // 128*20 = 2560 words

    const int t  = threadIdx.x;
    const int w  = t >> 5;
    const int ln = t & 31;
    const int mt = blockIdx.x;
    const int nt = blockIdx.y;
    const int b  = blockIdx.z;
    const int m0 = mt * 128;
    const int n0 = nt * 64;

    if (t < 128) {
        int mg = m0 + t;
        int rm = mg / WIMG;
        rc[t] = (rm << 8) | (mg - rm * WIMG);
    }

    const int g   = ln >> 2;
    const int tg  = ln & 3;
    const int nbw = (w & 1) * 32;
    const int mbw = (w >> 1) * 32;

    float acc[2][4][4];
#pragma unroll
    for (int i = 0; i < 2; i++)
#pragma unroll
        for (int j = 0; j < 4; j++)
#pragma unroll
            for (int k = 0; k < 4; k++) acc[i][j][k] = 0.f;

    const __half* Qh = g_Qh + ((size_t)b * NN + n0) * CC;
    const __half* Dh = g_Dh + ((size_t)b * NN + m0) * CC;

    for (int k0 = 0; k0 < CC; k0 += 32) {
        {
            int nrow = t >> 2, c4 = t & 3;
            uint4 v = ((const uint4*)(Qh + (size_t)nrow * CC + k0))[c4];
            *(uint4*)&As2[nrow * KPAD + c4 * 4] = v;
        }
#pragma unroll
        for (int i = 0; i < 2; i++) {
            int idx = t + i * 256;
            int m = idx >> 2, c4 = idx & 3;
            uint4 v = ((const uint4*)(Dh + (size_t)m * CC + k0))[c4];
            *(uint4*)&Bs2[m * KPAD + c4 * 4] = v;
        }
        __syncthreads();

#pragma unroll
        for (int kk = 0; kk < 2; kk++) {
            int kb = kk * 8 + tg;
            uint32_t af[2][4];
#pragma unroll
            for (int rt = 0; rt < 2; rt++) {
                int nb = nbw + rt * 16 + g;
                af[rt][0] = As2[nb * KPAD + kb];
                af[rt][1] = As2[(nb + 8) * KPAD + kb];
                af[rt][2] = As2[nb * KPAD + kb + 4];
                af[rt][3] = As2[(nb + 8) * KPAD + kb + 4];
            }
            uint32_t bf[4][2];
#pragma unroll
            for (int ct = 0; ct < 4; ct++) {
                int mb = mbw + ct * 8 + g;
                bf[ct][0] = Bs2[mb * KPAD + kb];
                bf[ct][1] = Bs2[mb * KPAD + kb + 4];
            }
#pragma unroll
            for (int rt = 0; rt < 2; rt++)
#pragma unroll
                for (int ct = 0; ct < 4; ct++)
                    mma_f16(acc[rt][ct], af[rt], bf[ct]);
        }
        __syncthreads();
    }

    // ---- write S tile to shared from HMMA fragments ----
#pragma unroll
    for (int rt = 0; rt < 2; rt++) {
        int row = nbw + rt * 16 + g;
#pragma unroll
        for (int ct = 0; ct < 4; ct++) {
            int col = mbw + ct * 8 + tg * 2;
            Ss[row * 129 + col]           = acc[rt][ct][0];
            Ss[row * 129 + col + 1]       = acc[rt][ct][1];
            Ss[(row + 8) * 129 + col]     = acc[rt][ct][2];
            Ss[(row + 8) * 129 + col + 1] = acc[rt][ct][3];
        }
    }
    __syncthreads();

    // ---- zero private hist columns (aliased w/ staging) ----
#pragma unroll
    for (int c = 0; c < 26; c++) { hN[c * 256 + t] = 0.f; hR[c * 256 + t] = 0.f; }

    // ---- binning ----
    {
        int r  = ((w & 1) << 5) | ln;
        int mq = w >> 1;
        int ng = n0 + r;
        int rn = ng / WIMG;
        int cn = ng - rn * WIMG;
        float* hNc = hN + t;
        float* hRc = hR + t;
#pragma unroll 4
        for (int m = 0; m < 32; m++) {
            int ml = mq * 32 + m;
            float s = Ss[r * 129 + ml];
            int rcm = rc[ml];
            int dr = (rcm >> 8) - rn;
            int dc = (rcm & 255) - cn;
            bool lab = (abs(dr) <= 4) && (abs(dc) <= 4);
            float tq = fmaf(s, -12.f, 12.f);
            tq = fminf(fmaxf(tq, 0.f), 24.f);
            float cf = floorf(tq);
            int c0 = (int)cf;
            float whi = tq - cf;
            float wlo = 1.f - whi;
            hNc[c0 * 256]       += wlo;
            hNc[c0 * 256 + 256] += whi;
            if (lab) {
                hRc[c0 * 256]       += wlo;
                hRc[c0 * 256 + 256] += whi;
            }
        }
    }
    __syncthreads();

    // ---- reduce 4 m-quarter partials per row, store partial hist to global ----
    float* outp = g_hist + ((size_t)(b * 18 + mt) * 52) * NN;
#pragma unroll
    for (int kk = 0; kk < 13; kk++) {
        int idx  = t + kk * 256;
        int slot = idx >> 6;
        int rr   = idx & 63;
        float* hh = (slot < 26) ? (hN + slot * 256) : (hR + (slot - 26) * 256);
        float v = 0.f;
#pragma unroll
        for (int q = 0; q < 4; q++) {
            int tq_ = ((((q << 1) | (rr >> 5)) << 5) | (rr & 31));
            v += hh[tq_];
        }
        outp[(size_t)slot * NN + n0 + rr] = v;
    }
}

// ---------------- kernel 4: reduce mt partials (coalesced, high parallelism) ------
// out g_hist2[b][s][n], s in 0..49: s<25 -> in-slot s (nbs), s>=25 -> in-slot s+1 (rec)
__global__ void k_red() {
    int id = blockIdx.x * 256 + threadIdx.x;      // 0..230399
    int n  = id % NN;
    int sb = id / NN;                              // 0..99
    int s  = sb % 50;
    int b  = sb / 50;
    int in_slot = s + (s >= 25 ? 1 : 0);
    const float* src = g_hist + ((size_t)(b * 18) * 52 + in_slot) * NN + n;
    float v = 0.f;
#pragma unroll
    for (int mt = 0; mt < 18; mt++) v += src[(size_t)mt * 52 * NN];
    g_hist2[((size_t)b * 50 + s) * NN + n] = v;
}

// ---------------- kernel 5: per-row AP + loss + last-block final reduce ----------------
__global__ void k_final1(const float* __restrict__ rel, float* __restrict__ out) {
    int id = blockIdx.x * 128 + threadIdx.x;   // 0..4607
    int b = id / NN;
    int n = id - b * NN;
    const float* h2 = g_hist2 + (size_t)b * 50 * NN + n;

    // prefetch all 50 values (independent loads -> MLP hides latency)
    float nbv[25], rcv[25];
#pragma unroll
    for (int c = 0; c < 25; c++) {
        nbv[c] = h2[(size_t)c * NN];
        rcv[c] = h2[(size_t)(25 + c) * NN];
    }

    float cumn = 0.f, cumr = 0.f, sap = 0.f, sr = 0.f;
#pragma unroll
    for (int c = 0; c < 25; c++) {
        cumn += nbv[c];
        cumr += rcv[c];
        float prec = cumr / (1e-16f + cumn);
        sap = fmaf(prec, rcv[c], sap);
        sr += rcv[c];
    }
    float ap = sap / sr;
    float rl = rel[(size_t)b * NN + n];
    float loss = 1.f - (ap * rl + 0.5f * (1.f - rl));

    __shared__ float red[128];
    red[threadIdx.x] = loss;
    __syncthreads();
#pragma unroll
    for (int s = 64; s > 0; s >>= 1) {
        if (threadIdx.x < s) red[threadIdx.x] += red[threadIdx.x + s];
        __syncthreads();
    }
    if (threadIdx.x == 0) {
        g_part[blockIdx.x] = red[0];
        __threadfence();
        unsigned old = atomicAdd(&g_ctr, 1u);
        if (old == 35u) {
            __threadfence();
            float ssum = 0.f;
#pragma unroll
            for (int i = 0; i < 36; i++) ssum += g_part[i];
            out[0] = ssum * (1.0f / 4608.0f);
            g_ctr = 0u;
        }
    }
}

// ---------------- launch ----------------
extern "C" void kernel_launch(void* const* d_in, const int* in_sizes, int n_in,
                              void* d_out, int out_size) {
    const float* img1 = (const float*)d_in[0];
    const float* img2 = (const float*)d_in[1];
    const float* rel  = (const float*)d_in[2];
    const float* grid = (const float*)d_in[3];

    cudaFuncSetAttribute(k_main, cudaFuncAttributeMaxDynamicSharedMemorySize,
                         SM_TOT * (int)sizeof(float));

    k_prep<<<dim3(72, 4, 4), dim3(32, 8)>>>(img1, img2);
    k_gridsample<<<dim3(288, 2), 256>>>(grid);
    k_main<<<dim3(18, 36, BZ), 256, SM_TOT * (int)sizeof(float)>>>();
    k_red<<<900, 256>>>();
    k_final1<<<36, 128>>>(rel, (float*)d_out);
}

// round 6
// speedup vs baseline: 2.8942x; 1.0535x over previous
#include <cuda_runtime.h>
#include <cuda_fp16.h>
#include <math.h>
#include <stdint.h>

#define BZ 2
#define CC 128
#define NN 2304
#define WIMG 48
#define MC 256          // m-chunk width
#define NCH 9           // 2304 / 256
#define BPAD 68         // u32 row stride for staged A/B (68 mod 32 == 4 -> frag reads conflict-free)
#define SSTR 257        // Ss row stride (floats), 257 mod 32 == 1 -> column reads conflict-free

// ---------------- scratch (no allocations allowed) ----------------
__device__ __half g_Qh[BZ * NN * CC];            // img1 transposed -> [b][n][c] half
__device__ __half g_Th[BZ * NN * CC];            // img2 transposed -> [b][p][c] half
__device__ __half g_Dh[BZ * NN * CC];            // grid-sampled db  [b][n][c] half
__device__ float g_hist2[(size_t)BZ * 50 * NN];  // reduced hists [b][slot50][n]
__device__ float g_part[36];
__device__ unsigned g_ctr = 0;

// ---------------- kernel 1: transpose [b][c][p] -> [b][p][c] + cvt to half ----------
__global__ void k_prep(const float* __restrict__ img1, const float* __restrict__ img2) {
    __shared__ float tile[32][33];
    int img = blockIdx.z & 1;
    int b   = blockIdx.z >> 1;
    const float* in = (img == 0 ? img1 : img2) + (size_t)b * CC * NN;
    __half* out     = (img == 0 ? g_Qh : g_Th) + (size_t)b * NN * CC;

    int p0 = blockIdx.x * 32;
    int c0 = blockIdx.y * 32;
    int tx = threadIdx.x, ty = threadIdx.y;

#pragma unroll
    for (int j = 0; j < 4; j++)
        tile[ty + j * 8][tx] = in[(size_t)(c0 + ty + j * 8) * NN + p0 + tx];
    __syncthreads();
#pragma unroll
    for (int j = 0; j < 4; j++)
        out[(size_t)(p0 + ty + j * 8) * CC + c0 + tx] =
            __float2half(tile[tx][ty + j * 8]);
}

// ---------------- kernel 2: grid_sample, warp-per-point, coalesced ----------------
__global__ void k_gridsample(const float* __restrict__ grid) {
    int w    = threadIdx.x >> 5;
    int lane = threadIdx.x & 31;
    int n = blockIdx.x * 8 + w;
    int b = blockIdx.y;

    float gx = grid[((size_t)b * NN + n) * 2 + 0];
    float gy = grid[((size_t)b * NN + n) * 2 + 1];
    float ix = fmaf(gx, 24.0f, 23.5f);
    float iy = fmaf(gy, 24.0f, 23.5f);
    float x0f = floorf(ix), y0f = floorf(iy);
    float wx = ix - x0f, wy = iy - y0f;
    int x0 = (int)x0f, y0 = (int)y0f;
    int x1 = x0 + 1,  y1 = y0 + 1;

    bool vx0 = (x0 >= 0) & (x0 < WIMG);
    bool vx1 = (x1 >= 0) & (x1 < WIMG);
    bool vy0 = (y0 >= 0) & (y0 < WIMG);
    bool vy1 = (y1 >= 0) & (y1 < WIMG);

    float w00 = (vx0 & vy0) ? (1.f - wx) * (1.f - wy) : 0.f;
    float w10 = (vx1 & vy0) ? wx * (1.f - wy)         : 0.f;
    float w01 = (vx0 & vy1) ? (1.f - wx) * wy         : 0.f;
    float w11 = (vx1 & vy1) ? wx * wy                 : 0.f;

    int cx0 = min(max(x0, 0), WIMG - 1), cx1 = min(max(x1, 0), WIMG - 1);
    int cy0 = min(max(y0, 0), WIMG - 1), cy1 = min(max(y1, 0), WIMG - 1);

    const __half* T = g_Th + (size_t)b * NN * CC;
    int p00 = cy0 * WIMG + cx0, p10 = cy0 * WIMG + cx1;
    int p01 = cy1 * WIMG + cx0, p11 = cy1 * WIMG + cx1;

    uint2 v00 = ((const uint2*)(T + (size_t)p00 * CC))[lane];
    uint2 v10 = ((const uint2*)(T + (size_t)p10 * CC))[lane];
    uint2 v01 = ((const uint2*)(T + (size_t)p01 * CC))[lane];
    uint2 v11 = ((const uint2*)(T + (size_t)p11 * CC))[lane];

    float r[4];
#pragma unroll
    for (int h = 0; h < 2; h++) {
        float2 f00 = __half22float2(((__half2*)&v00)[h]);
        float2 f10 = __half22float2(((__half2*)&v10)[h]);
        float2 f01 = __half22float2(((__half2*)&v01)[h]);
        float2 f11 = __half22float2(((__half2*)&v11)[h]);
        r[2 * h + 0] = w00 * f00.x + w10 * f10.x + w01 * f01.x + w11 * f11.x;
        r[2 * h + 1] = w00 * f00.y + w10 * f10.y + w01 * f01.y + w11 * f11.y;
    }
    uint2 o;
    ((__half2*)&o)[0] = __floats2half2_rn(r[0], r[1]);
    ((__half2*)&o)[1] = __floats2half2_rn(r[2], r[3]);
    ((uint2*)(g_Dh + ((size_t)b * NN + n) * CC))[lane] = o;
}

// ---------------- fp16 MMA helper ----------------
__device__ __forceinline__ void mma_f16(float* d, const uint32_t* a, const uint32_t* bb) {
    asm volatile(
        "mma.sync.aligned.m16n8k16.row.col.f32.f16.f16.f32 "
        "{%0,%1,%2,%3}, {%4,%5,%6,%7}, {%8,%9}, {%0,%1,%2,%3};"
        : "+f"(d[0]), "+f"(d[1]), "+f"(d[2]), "+f"(d[3])
        : "r"(a[0]), "r"(a[1]), "r"(a[2]), "r"(a[3]), "r"(bb[0]), "r"(bb[1]));
}

// ---------------- kernel 3: per-n-tile GEMM + binning, full m loop, direct hist out ----
// block = (nt 0..71, b). Tile: 32 n-rows; loops 9 chunks of 256 m. 256 threads, 1 block/SM.
// smem (floats):
#define SM_SS   0                          // 32*257   = 8224
#define SM_HN   (SM_SS + 32 * SSTR)        // 26*256   = 6656
#define SM_HR   (SM_HN + 26 * 256)         // 6656
#define SM_RC   (SM_HR + 26 * 256)         // 256 ints
#define SM_A    (SM_RC + 256)              // 32*68 u32  = 2176
#define SM_B    (SM_A + 32 * BPAD)         // 256*68 u32 = 17408
#define SM_TOT  (SM_B + 256 * BPAD)        // 41376 floats = 165.5 KB

__global__ void __launch_bounds__(256, 1) k_main() {
    extern __shared__ float smf[];
    float*    Ss  = smf + SM_SS;
    float*    hN  = smf + SM_HN;
    float*    hR  = smf + SM_HR;
    int*      rcM = (int*)(smf + SM_RC);
    uint32_t* As2 = (uint32_t*)(smf + SM_A);
    uint32_t* Bs2 = (uint32_t*)(smf + SM_B);

    const int t  = threadIdx.x;
    const int w  = t >> 5;
    const int ln = t & 31;
    const int g  = ln >> 2;
    const int tg = ln & 3;
    const int nt = blockIdx.x;
    const int b  = blockIdx.y;
    const int n0 = nt * 32;

    // zero private hist columns
#pragma unroll
    for (int c = 0; c < 26; c++) { hN[c * 256 + t] = 0.f; hR[c * 256 + t] = 0.f; }

    // stage A (32 queries x 128 c) once: 512 uint4, 2 per thread
    const __half* Qh = g_Qh + ((size_t)b * NN + n0) * CC;
#pragma unroll
    for (int i = 0; i < 2; i++) {
        int idx = t + i * 256;
        int row = idx >> 4, c4 = idx & 15;
        uint4 v = ((const uint4*)(Qh + (size_t)row * CC))[c4];
        *(uint4*)&As2[row * BPAD + c4 * 4] = v;
    }

    // binning row identity (invariant): lane = row
    const int ng = n0 + ln;
    const int rn = ng / WIMG;
    const int cn = ng - rn * WIMG;

    const __half* Dh = g_Dh + (size_t)b * NN * CC;

    for (int mc = 0; mc < NCH; mc++) {
        const int m0 = mc * MC;
        // stage B chunk (256 db rows x 128 c): 4096 uint4, 16 per thread
#pragma unroll
        for (int i = 0; i < 16; i++) {
            int idx = t + i * 256;
            int m = idx >> 4, c4 = idx & 15;
            uint4 v = ((const uint4*)(Dh + (size_t)(m0 + m) * CC))[c4];
            *(uint4*)&Bs2[m * BPAD + c4 * 4] = v;
        }
        // m row/col codes for this chunk
        {
            int mg = m0 + t;
            int rm = mg / WIMG;
            rcM[t] = (rm << 8) | (mg - rm * WIMG);
        }
        __syncthreads();

        // ---- GEMM: warp w covers all 32 rows x cols [w*32, w*32+32) ----
        float acc[2][4][4];
#pragma unroll
        for (int i = 0; i < 2; i++)
#pragma unroll
            for (int j = 0; j < 4; j++)
#pragma unroll
                for (int k = 0; k < 4; k++) acc[i][j][k] = 0.f;

#pragma unroll
        for (int kk = 0; kk < 8; kk++) {
            int kb = kk * 8 + tg;
            uint32_t af[2][4];
#pragma unroll
            for (int rt = 0; rt < 2; rt++) {
                int nb = rt * 16 + g;
                af[rt][0] = As2[nb * BPAD + kb];
                af[rt][1] = As2[(nb + 8) * BPAD + kb];
                af[rt][2] = As2[nb * BPAD + kb + 4];
                af[rt][3] = As2[(nb + 8) * BPAD + kb + 4];
            }
            uint32_t bf[4][2];
#pragma unroll
            for (int ct = 0; ct < 4; ct++) {
                int mb = w * 32 + ct * 8 + g;
                bf[ct][0] = Bs2[mb * BPAD + kb];
                bf[ct][1] = Bs2[mb * BPAD + kb + 4];
            }
#pragma unroll
            for (int rt = 0; rt < 2; rt++)
#pragma unroll
                for (int ct = 0; ct < 4; ct++)
                    mma_f16(acc[rt][ct], af[rt], bf[ct]);
        }

        // ---- fragments -> Ss ----
#pragma unroll
        for (int rt = 0; rt < 2; rt++) {
            int row = rt * 16 + g;
#pragma unroll
            for (int ct = 0; ct < 4; ct++) {
                int col = w * 32 + ct * 8 + tg * 2;
                Ss[row * SSTR + col]           = acc[rt][ct][0];
                Ss[row * SSTR + col + 1]       = acc[rt][ct][1];
                Ss[(row + 8) * SSTR + col]     = acc[rt][ct][2];
                Ss[(row + 8) * SSTR + col + 1] = acc[rt][ct][3];
            }
        }
        __syncthreads();

        // ---- binning: lane = row, warp w covers m-slice [w*32, w*32+32) ----
        {
            float* hNc = hN + t;
            float* hRc = hR + t;
#pragma unroll 4
            for (int m = 0; m < 32; m++) {
                int ml = w * 32 + m;
                float s = Ss[ln * SSTR + ml];
                int rcm = rcM[ml];
                int dr = (rcm >> 8) - rn;
                int dc = (rcm & 255) - cn;
                bool lab = (abs(dr) <= 4) && (abs(dc) <= 4);
                float tq = fmaf(s, -12.f, 12.f);
                tq = fminf(fmaxf(tq, 0.f), 24.f);
                float cf = floorf(tq);
                int c0 = (int)cf;
                float whi = tq - cf;
                float wlo = 1.f - whi;
                hNc[c0 * 256]       += wlo;
                hNc[c0 * 256 + 256] += whi;
                if (__any_sync(0xffffffffu, lab)) {
                    if (lab) {
                        hRc[c0 * 256]       += wlo;
                        hRc[c0 * 256 + 256] += whi;
                    }
                }
            }
        }
        __syncthreads();   // protect Bs2/rcM for next chunk
    }

    // ---- flush: reduce 8 warp-columns per (slot, row), write g_hist2 directly ----
    // row r contributors: columns t = w8*32 + r, w8 = 0..7
#pragma unroll
    for (int kk = 0; kk < 7; kk++) {
        int idx = t + kk * 256;            // 0..1599 used
        if (idx < 1600) {
            int s50 = idx >> 5;            // 0..49
            int r   = idx & 31;
            float* hh = (s50 < 25) ? (hN + s50 * 256) : (hR + (s50 - 25) * 256);
            float v = 0.f;
#pragma unroll
            for (int w8 = 0; w8 < 8; w8++) v += hh[w8 * 32 + r];
            g_hist2[((size_t)(b * 50 + s50)) * NN + n0 + r] = v;
        }
    }
}

// ---------------- kernel 4: per-row AP + loss + last-block final reduce ----------------
__global__ void k_final1(const float* __restrict__ rel, float* __restrict__ out) {
    int id = blockIdx.x * 128 + threadIdx.x;   // 0..4607
    int b = id / NN;
    int n = id - b * NN;
    const float* h2 = g_hist2 + (size_t)b * 50 * NN + n;

    float nbv[25], rcv[25];
#pragma unroll
    for (int c = 0; c < 25; c++) {
        nbv[c] = h2[(size_t)c * NN];
        rcv[c] = h2[(size_t)(25 + c) * NN];
    }

    float cumn = 0.f, cumr = 0.f, sap = 0.f, sr = 0.f;
#pragma unroll
    for (int c = 0; c < 25; c++) {
        cumn += nbv[c];
        cumr += rcv[c];
        float prec = cumr / (1e-16f + cumn);
        sap = fmaf(prec, rcv[c], sap);
        sr += rcv[c];
    }
    float ap = sap / sr;
    float rl = rel[(size_t)b * NN + n];
    float loss = 1.f - (ap * rl + 0.5f * (1.f - rl));

    __shared__ float red[128];
    red[threadIdx.x] = loss;
    __syncthreads();
#pragma unroll
    for (int s = 64; s > 0; s >>= 1) {
        if (threadIdx.x < s) red[threadIdx.x] += red[threadIdx.x + s];
        __syncthreads();
    }
    if (threadIdx.x == 0) {
        g_part[blockIdx.x] = red[0];
        __threadfence();
        unsigned old = atomicAdd(&g_ctr, 1u);
        if (old == 35u) {
            __threadfence();
            float ssum = 0.f;
#pragma unroll
            for (int i = 0; i < 36; i++) ssum += g_part[i];
            out[0] = ssum * (1.0f / 4608.0f);
            g_ctr = 0u;
        }
    }
}

// ---------------- launch ----------------
extern "C" void kernel_launch(void* const* d_in, const int* in_sizes, int n_in,
                              void* d_out, int out_size) {
    const float* img1 = (const float*)d_in[0];
    const float* img2 = (const float*)d_in[1];
    const float* rel  = (const float*)d_in[2];
    const float* grid = (const float*)d_in[3];

    cudaFuncSetAttribute(k_main, cudaFuncAttributeMaxDynamicSharedMemorySize,
                         SM_TOT * (int)sizeof(float));

    k_prep<<<dim3(72, 4, 4), dim3(32, 8)>>>(img1, img2);
    k_gridsample<<<dim3(288, 2), 256>>>(grid);
    k_main<<<dim3(72, 2), 256, SM_TOT * (int)sizeof(float)>>>();
    k_final1<<<36, 128>>>(rel, (float*)d_out);
}